// round 1
// baseline (speedup 1.0000x reference)
#include <cuda_runtime.h>

typedef unsigned long long u64;

#define B_ 32
#define N_ 64
#define D_ 256
#define C_ 8192

// Scratch (static device memory — no runtime allocation).
__device__ float g_Wt[(size_t)C_ * D_];          // codebook_w transposed [C, D], 32 MB
__device__ float g_q1p[4][(size_t)B_ * N_ * D_]; // K-split partials of z@W^T, 8 MB

// ---------- packed f32x2 helpers (FFMA2) ----------
__device__ __forceinline__ u64 splat2(float x) {
    u64 r; unsigned xi = __float_as_uint(x);
    asm("mov.b64 %0, {%1, %1};" : "=l"(r) : "r"(xi));
    return r;
}
__device__ __forceinline__ void ffma2(u64 &d, u64 a, u64 b) {
    asm("fma.rn.f32x2 %0, %1, %2, %0;" : "+l"(d) : "l"(a), "l"(b));
}
__device__ __forceinline__ float2 unpack2(u64 v) {
    unsigned lo, hi;
    asm("mov.b64 {%0, %1}, %2;" : "=r"(lo), "=r"(hi) : "l"(v));
    return make_float2(__uint_as_float(lo), __uint_as_float(hi));
}

// ---------- Kernel 1: log_alpha[b,n,c] = sum_k logits[b,n,k] * head[n,k,c] ----------
// grid (C/256, N), block 128. Block tile: all 32 b-rows x 256 c-cols.
// Thread tile: 16 rows x 4 cols, rows packed in f32x2 pairs.
__global__ __launch_bounds__(128) void k_gemm_head(
    const float* __restrict__ logits, const float* __restrict__ head,
    float* __restrict__ la)
{
    __shared__ __align__(16) float As[256 * 36];  // As[k*36 + b] (padded stride)
    const int n  = blockIdx.y;
    const int cb = blockIdx.x * 256;
    const int tid = threadIdx.x;

    for (int i = tid; i < B_ * D_; i += 128) {
        int b = i >> 8, k = i & 255;
        As[k * 36 + b] = logits[((size_t)b * N_ + n) * D_ + k];
    }
    __syncthreads();

    const int cg = tid & 63, rg = tid >> 6;
    const int c  = cb + cg * 4;
    const int r0 = rg * 16;

    u64 acc[8][4];
    #pragma unroll
    for (int p = 0; p < 8; p++)
        #pragma unroll
        for (int j = 0; j < 4; j++) acc[p][j] = 0ull;

    const float* hp = head + (size_t)n * D_ * C_ + c;
    #pragma unroll 4
    for (int k = 0; k < 256; k++) {
        float4 h = *reinterpret_cast<const float4*>(hp + (size_t)k * C_);
        u64 h0 = splat2(h.x), h1 = splat2(h.y), h2 = splat2(h.z), h3 = splat2(h.w);
        const u64* ap = reinterpret_cast<const u64*>(&As[k * 36 + r0]);
        #pragma unroll
        for (int p = 0; p < 8; p++) {
            u64 a2 = ap[p];
            ffma2(acc[p][0], a2, h0);
            ffma2(acc[p][1], a2, h1);
            ffma2(acc[p][2], a2, h2);
            ffma2(acc[p][3], a2, h3);
        }
    }

    #pragma unroll
    for (int p = 0; p < 8; p++) {
        float2 v0 = unpack2(acc[p][0]), v1 = unpack2(acc[p][1]);
        float2 v2 = unpack2(acc[p][2]), v3 = unpack2(acc[p][3]);
        int rlo = r0 + 2 * p;
        float4 lo = make_float4(v0.x, v1.x, v2.x, v3.x);
        float4 hi = make_float4(v0.y, v1.y, v2.y, v3.y);
        *reinterpret_cast<float4*>(&la[((size_t)rlo * N_ + n) * C_ + c]) = lo;
        *reinterpret_cast<float4*>(&la[((size_t)(rlo + 1) * N_ + n) * C_ + c]) = hi;
    }
}

// ---------- Kernel 2: z = softmax((la + gumbel)/tau) over C per (b,n) row ----------
__global__ __launch_bounds__(256) void k_softmax(
    const float* __restrict__ la, const float* __restrict__ gum,
    const float* __restrict__ tau, float* __restrict__ z)
{
    __shared__ __align__(16) float sv[C_];
    __shared__ float redm[8];
    __shared__ float reds[8];
    const int m = blockIdx.x;
    const size_t base = (size_t)m * C_;
    const float inv_tau = 1.0f / tau[0];
    const int tid = threadIdx.x;
    const int w = tid >> 5, l = tid & 31;

    float lmax = -3.4e38f;
    for (int c = tid * 4; c < C_; c += 1024) {
        float4 a = *reinterpret_cast<const float4*>(&la[base + c]);
        float4 g = *reinterpret_cast<const float4*>(&gum[base + c]);
        float4 v;
        v.x = (a.x + g.x) * inv_tau;
        v.y = (a.y + g.y) * inv_tau;
        v.z = (a.z + g.z) * inv_tau;
        v.w = (a.w + g.w) * inv_tau;
        *reinterpret_cast<float4*>(&sv[c]) = v;
        lmax = fmaxf(lmax, fmaxf(fmaxf(v.x, v.y), fmaxf(v.z, v.w)));
    }
    #pragma unroll
    for (int off = 16; off; off >>= 1)
        lmax = fmaxf(lmax, __shfl_xor_sync(0xffffffffu, lmax, off));
    if (l == 0) redm[w] = lmax;
    __syncthreads();
    float bmax = redm[0];
    #pragma unroll
    for (int i = 1; i < 8; i++) bmax = fmaxf(bmax, redm[i]);

    float lsum = 0.0f;
    for (int c = tid * 4; c < C_; c += 1024) {
        float4 v = *reinterpret_cast<const float4*>(&sv[c]);
        v.x = __expf(v.x - bmax);
        v.y = __expf(v.y - bmax);
        v.z = __expf(v.z - bmax);
        v.w = __expf(v.w - bmax);
        *reinterpret_cast<float4*>(&sv[c]) = v;
        lsum += (v.x + v.y) + (v.z + v.w);
    }
    #pragma unroll
    for (int off = 16; off; off >>= 1)
        lsum += __shfl_xor_sync(0xffffffffu, lsum, off);
    if (l == 0) reds[w] = lsum;
    __syncthreads();
    float bsum = 0.0f;
    #pragma unroll
    for (int i = 0; i < 8; i++) bsum += reds[i];
    const float inv = 1.0f / bsum;

    for (int c = tid * 4; c < C_; c += 1024) {
        float4 v = *reinterpret_cast<const float4*>(&sv[c]);
        v.x *= inv; v.y *= inv; v.z *= inv; v.w *= inv;
        *reinterpret_cast<float4*>(&z[base + c]) = v;
    }
}

// ---------- Kernel 3: transpose codebook_w [D,C] -> g_Wt [C,D] ----------
__global__ void k_transpose(const float* __restrict__ W)
{
    __shared__ float t[32][33];
    int cx = blockIdx.x * 32 + threadIdx.x;  // c
    int dy = blockIdx.y * 32 + threadIdx.y;  // d
    #pragma unroll
    for (int j = 0; j < 32; j += 8)
        t[threadIdx.y + j][threadIdx.x] = W[(size_t)(dy + j) * C_ + cx];
    __syncthreads();
    int dx = blockIdx.y * 32 + threadIdx.x;  // d
    int cy = blockIdx.x * 32 + threadIdx.y;  // c
    #pragma unroll
    for (int j = 0; j < 32; j += 8)
        g_Wt[(size_t)(cy + j) * D_ + dx] = t[threadIdx.x][threadIdx.y + j];
}

// ---------- Kernel 4: q1[m,d] = sum_c z[m,c] * Wt[c,d], K-split into 4 partials ----------
// grid (2, 64, 4), block 128. Block tile 32 m-rows x 128 d-cols, K=2048 slice.
// Thread tile: 8 rows x 4 cols, rows packed in f32x2 pairs.
__global__ __launch_bounds__(128) void k_gemm_cb(const float* __restrict__ z)
{
    __shared__ __align__(16) float zs[256 * 36];  // zs[c*36 + r]
    const int m0 = blockIdx.y * 32;
    const int d0 = blockIdx.x * 128;
    const int k0 = blockIdx.z * 2048;
    float* part = g_q1p[blockIdx.z];
    const int tid = threadIdx.x;
    const int dg = tid & 31, mg = tid >> 5;
    const int d  = d0 + dg * 4;
    const int r0 = mg * 8;

    u64 acc[4][4];
    #pragma unroll
    for (int p = 0; p < 4; p++)
        #pragma unroll
        for (int j = 0; j < 4; j++) acc[p][j] = 0ull;

    for (int ck = k0; ck < k0 + 2048; ck += 256) {
        __syncthreads();
        for (int i = tid; i < 32 * 256; i += 128) {
            int r = i >> 8, cc = i & 255;
            zs[cc * 36 + r] = z[(size_t)(m0 + r) * C_ + ck + cc];
        }
        __syncthreads();
        #pragma unroll 4
        for (int cc = 0; cc < 256; cc++) {
            float4 w = *reinterpret_cast<const float4*>(&g_Wt[(size_t)(ck + cc) * D_ + d]);
            u64 w0 = splat2(w.x), w1 = splat2(w.y), w2 = splat2(w.z), w3 = splat2(w.w);
            const u64* ap = reinterpret_cast<const u64*>(&zs[cc * 36 + r0]);
            #pragma unroll
            for (int p = 0; p < 4; p++) {
                u64 a2 = ap[p];
                ffma2(acc[p][0], a2, w0);
                ffma2(acc[p][1], a2, w1);
                ffma2(acc[p][2], a2, w2);
                ffma2(acc[p][3], a2, w3);
            }
        }
    }

    #pragma unroll
    for (int p = 0; p < 4; p++) {
        float2 v0 = unpack2(acc[p][0]), v1 = unpack2(acc[p][1]);
        float2 v2 = unpack2(acc[p][2]), v3 = unpack2(acc[p][3]);
        int rlo = m0 + r0 + 2 * p;
        float4 lo = make_float4(v0.x, v1.x, v2.x, v3.x);
        float4 hi = make_float4(v0.y, v1.y, v2.y, v3.y);
        *reinterpret_cast<float4*>(&part[(size_t)rlo * D_ + d]) = lo;
        *reinterpret_cast<float4*>(&part[(size_t)(rlo + 1) * D_ + d]) = hi;
    }
}

// ---------- Kernel 5: quantized[b,n,j] = sum_d q1[b,n,d] * pos_map[n,d,j] ----------
// grid N, block 256. Sums the 4 K-split partials while staging q1 in smem.
__global__ __launch_bounds__(256) void k_posmap(
    const float* __restrict__ pm, float* __restrict__ outq)
{
    __shared__ __align__(16) float qs[256 * 36];  // qs[d*36 + b]
    const int n = blockIdx.x;
    const int tid = threadIdx.x;

    for (int i = tid; i < 32 * 256; i += 256) {
        int b = i >> 8, dd = i & 255;
        size_t idx = ((size_t)b * N_ + n) * D_ + dd;
        qs[dd * 36 + b] = g_q1p[0][idx] + g_q1p[1][idx] + g_q1p[2][idx] + g_q1p[3][idx];
    }
    __syncthreads();

    const int jg = tid & 127, rg = tid >> 7;
    const int j  = jg * 2, r0 = rg * 16;

    u64 acc[8][2];
    #pragma unroll
    for (int p = 0; p < 8; p++) { acc[p][0] = 0ull; acc[p][1] = 0ull; }

    #pragma unroll 4
    for (int dd = 0; dd < 256; dd++) {
        float2 w = *reinterpret_cast<const float2*>(&pm[((size_t)n * D_ + dd) * D_ + j]);
        u64 w0 = splat2(w.x), w1 = splat2(w.y);
        const u64* ap = reinterpret_cast<const u64*>(&qs[dd * 36 + r0]);
        #pragma unroll
        for (int p = 0; p < 8; p++) {
            u64 a2 = ap[p];
            ffma2(acc[p][0], a2, w0);
            ffma2(acc[p][1], a2, w1);
        }
    }

    #pragma unroll
    for (int p = 0; p < 8; p++) {
        float2 v0 = unpack2(acc[p][0]);  // col j   (rows rlo, rlo+1)
        float2 v1 = unpack2(acc[p][1]);  // col j+1
        int rlo = r0 + 2 * p;
        float2 lo = make_float2(v0.x, v1.x);
        float2 hi = make_float2(v0.y, v1.y);
        *reinterpret_cast<float2*>(&outq[((size_t)rlo * N_ + n) * D_ + j]) = lo;
        *reinterpret_cast<float2*>(&outq[((size_t)(rlo + 1) * N_ + n) * D_ + j]) = hi;
    }
}

extern "C" void kernel_launch(void* const* d_in, const int* in_sizes, int n_in,
                              void* d_out, int out_size)
{
    const float* logits  = (const float*)d_in[0];  // [B,N,D]
    const float* head    = (const float*)d_in[1];  // [N,D,C]
    const float* pos_map = (const float*)d_in[2];  // [N,D,D]
    const float* cbw     = (const float*)d_in[3];  // [D,C]
    const float* gum     = (const float*)d_in[4];  // [B,N,C]
    const float* tau     = (const float*)d_in[5];  // [1]

    float* out  = (float*)d_out;
    float* outq = out;                                   // quantized [B,N,D]
    float* la   = out + (size_t)B_ * N_ * D_;            // log_alpha [B,N,C]
    float* z    = la + (size_t)B_ * N_ * C_;             // z [B,N,C]

    k_transpose<<<dim3(C_ / 32, D_ / 32), dim3(32, 8)>>>(cbw);
    k_gemm_head<<<dim3(C_ / 256, N_), 128>>>(logits, head, la);
    k_softmax<<<B_ * N_, 256>>>(la, gum, tau, z);
    k_gemm_cb<<<dim3(2, 64, 4), 128>>>(z);
    k_posmap<<<N_, 256>>>(pos_map, outq);
}

// round 2
// speedup vs baseline: 1.1255x; 1.1255x over previous
#include <cuda_runtime.h>

typedef unsigned long long u64;

#define B_ 32
#define N_ 64
#define D_ 256
#define C_ 8192
#define KSPLIT 16

// Scratch (static device memory — no runtime allocation).
__device__ float g_Wt[(size_t)C_ * D_];               // codebook_w transposed [C, D], 8 MB
__device__ float g_q1p[KSPLIT][(size_t)B_ * N_ * D_]; // K-split partials of z@W^T, 32 MB

// ---------- packed f32x2 helpers (FFMA2) ----------
__device__ __forceinline__ u64 splat2(float x) {
    u64 r; unsigned xi = __float_as_uint(x);
    asm("mov.b64 %0, {%1, %1};" : "=l"(r) : "r"(xi));
    return r;
}
__device__ __forceinline__ void ffma2(u64 &d, u64 a, u64 b) {
    asm("fma.rn.f32x2 %0, %1, %2, %0;" : "+l"(d) : "l"(a), "l"(b));
}
__device__ __forceinline__ float2 unpack2(u64 v) {
    unsigned lo, hi;
    asm("mov.b64 {%0, %1}, %2;" : "=r"(lo), "=r"(hi) : "l"(v));
    return make_float2(__uint_as_float(lo), __uint_as_float(hi));
}

// ---------- Kernel 1: log_alpha[b,n,c] = sum_k logits[b,n,k] * head[n,k,c] ----------
// grid (32, 64), block 128. Block tile: 32 b-rows x 256 c-cols, K=256.
// d-packed: thread tile 8 rows x 8 cols (4 u64 col-pairs). B loads straight from
// global as u64 pairs (no splat); A is a smem scalar broadcast + splat.
__global__ __launch_bounds__(128, 4) void k_gemm_head(
    const float* __restrict__ logits, const float* __restrict__ head,
    float* __restrict__ la)
{
    __shared__ __align__(16) float ls[32 * 260];   // ls[b*260 + k], pad 4
    const int n  = blockIdx.y;
    const int cb = blockIdx.x * 256;
    const int tid = threadIdx.x;

    // stage logits tile [32][256], float4 conflict-free
    #pragma unroll
    for (int j = 0; j < 16; j++) {
        int idx = tid + j * 128;           // [0, 2048)
        int b  = idx >> 6;
        int k4 = idx & 63;
        *reinterpret_cast<float4*>(&ls[b * 260 + 4 * k4]) =
            *reinterpret_cast<const float4*>(&logits[((size_t)b * N_ + n) * D_ + 4 * k4]);
    }
    __syncthreads();

    const int w = tid >> 5, lane = tid & 31;
    const int r0 = 8 * w;                  // 8 b-rows per warp
    const int c0 = cb + 8 * lane;          // 8 c-cols per lane

    u64 acc[8][4];
    #pragma unroll
    for (int i = 0; i < 8; i++)
        #pragma unroll
        for (int j = 0; j < 4; j++) acc[i][j] = 0ull;

    const float* hp = head + (size_t)n * D_ * C_ + c0;
    ulonglong2 wA = *reinterpret_cast<const ulonglong2*>(hp);
    ulonglong2 wB = *reinterpret_cast<const ulonglong2*>(hp + 4);

    #pragma unroll 4
    for (int k = 0; k < 256; k++) {
        const float* np = hp + (size_t)((k + 1) & 255) * C_;
        ulonglong2 nA = *reinterpret_cast<const ulonglong2*>(np);
        ulonglong2 nB = *reinterpret_cast<const ulonglong2*>(np + 4);

        u64 a[8];
        #pragma unroll
        for (int i = 0; i < 8; i++) a[i] = splat2(ls[(r0 + i) * 260 + k]);

        #pragma unroll
        for (int i = 0; i < 8; i++) {
            ffma2(acc[i][0], a[i], wA.x);
            ffma2(acc[i][1], a[i], wA.y);
            ffma2(acc[i][2], a[i], wB.x);
            ffma2(acc[i][3], a[i], wB.y);
        }
        wA = nA; wB = nB;
    }

    #pragma unroll
    for (int i = 0; i < 8; i++) {
        size_t base = ((size_t)(r0 + i) * N_ + n) * C_ + c0;
        *reinterpret_cast<u64*>(&la[base + 0]) = acc[i][0];
        *reinterpret_cast<u64*>(&la[base + 2]) = acc[i][1];
        *reinterpret_cast<u64*>(&la[base + 4]) = acc[i][2];
        *reinterpret_cast<u64*>(&la[base + 6]) = acc[i][3];
    }
}

// ---------- Kernel 2: z = softmax((la + gumbel)/tau) over C per (b,n) row ----------
__global__ __launch_bounds__(256) void k_softmax(
    const float* __restrict__ la, const float* __restrict__ gum,
    const float* __restrict__ tau, float* __restrict__ z)
{
    __shared__ __align__(16) float sv[C_];
    __shared__ float redm[8];
    __shared__ float reds[8];
    const int m = blockIdx.x;
    const size_t base = (size_t)m * C_;
    const float inv_tau = 1.0f / tau[0];
    const int tid = threadIdx.x;
    const int w = tid >> 5, l = tid & 31;

    float lmax = -3.4e38f;
    for (int c = tid * 4; c < C_; c += 1024) {
        float4 a = *reinterpret_cast<const float4*>(&la[base + c]);
        float4 g = *reinterpret_cast<const float4*>(&gum[base + c]);
        float4 v;
        v.x = (a.x + g.x) * inv_tau;
        v.y = (a.y + g.y) * inv_tau;
        v.z = (a.z + g.z) * inv_tau;
        v.w = (a.w + g.w) * inv_tau;
        *reinterpret_cast<float4*>(&sv[c]) = v;
        lmax = fmaxf(lmax, fmaxf(fmaxf(v.x, v.y), fmaxf(v.z, v.w)));
    }
    #pragma unroll
    for (int off = 16; off; off >>= 1)
        lmax = fmaxf(lmax, __shfl_xor_sync(0xffffffffu, lmax, off));
    if (l == 0) redm[w] = lmax;
    __syncthreads();
    float bmax = redm[0];
    #pragma unroll
    for (int i = 1; i < 8; i++) bmax = fmaxf(bmax, redm[i]);

    float lsum = 0.0f;
    for (int c = tid * 4; c < C_; c += 1024) {
        float4 v = *reinterpret_cast<const float4*>(&sv[c]);
        v.x = __expf(v.x - bmax);
        v.y = __expf(v.y - bmax);
        v.z = __expf(v.z - bmax);
        v.w = __expf(v.w - bmax);
        *reinterpret_cast<float4*>(&sv[c]) = v;
        lsum += (v.x + v.y) + (v.z + v.w);
    }
    #pragma unroll
    for (int off = 16; off; off >>= 1)
        lsum += __shfl_xor_sync(0xffffffffu, lsum, off);
    if (l == 0) reds[w] = lsum;
    __syncthreads();
    float bsum = 0.0f;
    #pragma unroll
    for (int i = 0; i < 8; i++) bsum += reds[i];
    const float inv = 1.0f / bsum;

    for (int c = tid * 4; c < C_; c += 1024) {
        float4 v = *reinterpret_cast<const float4*>(&sv[c]);
        v.x *= inv; v.y *= inv; v.z *= inv; v.w *= inv;
        *reinterpret_cast<float4*>(&z[base + c]) = v;
    }
}

// ---------- Kernel 3: transpose codebook_w [D,C] -> g_Wt [C,D] ----------
__global__ void k_transpose(const float* __restrict__ W)
{
    __shared__ float t[32][33];
    int cx = blockIdx.x * 32 + threadIdx.x;  // c
    int dy = blockIdx.y * 32 + threadIdx.y;  // d
    #pragma unroll
    for (int j = 0; j < 32; j += 8)
        t[threadIdx.y + j][threadIdx.x] = W[(size_t)(dy + j) * C_ + cx];
    __syncthreads();
    int dx = blockIdx.y * 32 + threadIdx.x;  // d
    int cy = blockIdx.x * 32 + threadIdx.y;  // c
    #pragma unroll
    for (int j = 0; j < 32; j += 8)
        g_Wt[(size_t)(cy + j) * D_ + dx] = t[threadIdx.x][threadIdx.y + j];
}

// ---------- Kernel 4: q1[m,d] = sum_c z[m,c] * Wt[c,d], K-split into 16 partials ----------
// grid (64, 16), block 128. Block tile 32 m-rows x all 256 d-cols, K=512 slice,
// staged in chunks of 128. d-packed thread tile 8 rows x 8 cols.
__global__ __launch_bounds__(128, 4) void k_gemm_cb(const float* __restrict__ z)
{
    __shared__ __align__(16) float zs[32 * 132];   // zs[r*132 + kk], pad 4
    const int m0 = blockIdx.x * 32;
    const int k0 = blockIdx.y * 512;
    float* part = g_q1p[blockIdx.y];
    const int tid = threadIdx.x;
    const int w = tid >> 5, lane = tid & 31;
    const int r0 = 8 * w;
    const int d0 = 8 * lane;

    u64 acc[8][4];
    #pragma unroll
    for (int i = 0; i < 8; i++)
        #pragma unroll
        for (int j = 0; j < 4; j++) acc[i][j] = 0ull;

    for (int ck = k0; ck < k0 + 512; ck += 128) {
        __syncthreads();
        #pragma unroll
        for (int j = 0; j < 8; j++) {
            int idx = tid + j * 128;      // [0, 1024)
            int r  = idx >> 5;
            int cq = idx & 31;
            *reinterpret_cast<float4*>(&zs[r * 132 + 4 * cq]) =
                *reinterpret_cast<const float4*>(&z[(size_t)(m0 + r) * C_ + ck + 4 * cq]);
        }
        __syncthreads();

        const float* wp = g_Wt + (size_t)ck * D_ + d0;
        ulonglong2 wA = *reinterpret_cast<const ulonglong2*>(wp);
        ulonglong2 wB = *reinterpret_cast<const ulonglong2*>(wp + 4);

        #pragma unroll 4
        for (int kk = 0; kk < 128; kk++) {
            const float* np = wp + (size_t)((kk + 1) & 127) * D_;
            ulonglong2 nA = *reinterpret_cast<const ulonglong2*>(np);
            ulonglong2 nB = *reinterpret_cast<const ulonglong2*>(np + 4);

            u64 a[8];
            #pragma unroll
            for (int i = 0; i < 8; i++) a[i] = splat2(zs[(r0 + i) * 132 + kk]);

            #pragma unroll
            for (int i = 0; i < 8; i++) {
                ffma2(acc[i][0], a[i], wA.x);
                ffma2(acc[i][1], a[i], wA.y);
                ffma2(acc[i][2], a[i], wB.x);
                ffma2(acc[i][3], a[i], wB.y);
            }
            wA = nA; wB = nB;
        }
    }

    #pragma unroll
    for (int i = 0; i < 8; i++) {
        size_t base = (size_t)(m0 + r0 + i) * D_ + d0;
        *reinterpret_cast<u64*>(&part[base + 0]) = acc[i][0];
        *reinterpret_cast<u64*>(&part[base + 2]) = acc[i][1];
        *reinterpret_cast<u64*>(&part[base + 4]) = acc[i][2];
        *reinterpret_cast<u64*>(&part[base + 6]) = acc[i][3];
    }
}

// ---------- Kernel 5: quantized[b,n,j] = sum_d q1[b,n,d] * pos_map[n,d,j] ----------
// grid N, block 256. Sums the 16 K-split partials while staging q1 in smem.
__global__ __launch_bounds__(256) void k_posmap(
    const float* __restrict__ pm, float* __restrict__ outq)
{
    __shared__ __align__(16) float qs[256 * 36];  // qs[d*36 + b]
    const int n = blockIdx.x;
    const int tid = threadIdx.x;

    for (int i = tid; i < 32 * 256; i += 256) {
        int b = i >> 8, dd = i & 255;
        size_t idx = ((size_t)b * N_ + n) * D_ + dd;
        float s = 0.0f;
        #pragma unroll
        for (int p = 0; p < KSPLIT; p++) s += g_q1p[p][idx];
        qs[dd * 36 + b] = s;
    }
    __syncthreads();

    const int jg = tid & 127, rg = tid >> 7;
    const int j  = jg * 2, r0 = rg * 16;

    u64 acc[8][2];
    #pragma unroll
    for (int p = 0; p < 8; p++) { acc[p][0] = 0ull; acc[p][1] = 0ull; }

    #pragma unroll 4
    for (int dd = 0; dd < 256; dd++) {
        float2 wv = *reinterpret_cast<const float2*>(&pm[((size_t)n * D_ + dd) * D_ + j]);
        u64 w0 = splat2(wv.x), w1 = splat2(wv.y);
        const u64* ap = reinterpret_cast<const u64*>(&qs[dd * 36 + r0]);
        #pragma unroll
        for (int p = 0; p < 8; p++) {
            u64 a2 = ap[p];
            ffma2(acc[p][0], a2, w0);
            ffma2(acc[p][1], a2, w1);
        }
    }

    #pragma unroll
    for (int p = 0; p < 8; p++) {
        float2 v0 = unpack2(acc[p][0]);  // col j   (rows rlo, rlo+1)
        float2 v1 = unpack2(acc[p][1]);  // col j+1
        int rlo = r0 + 2 * p;
        float2 lo = make_float2(v0.x, v1.x);
        float2 hi = make_float2(v0.y, v1.y);
        *reinterpret_cast<float2*>(&outq[((size_t)rlo * N_ + n) * D_ + j]) = lo;
        *reinterpret_cast<float2*>(&outq[((size_t)(rlo + 1) * N_ + n) * D_ + j]) = hi;
    }
}

extern "C" void kernel_launch(void* const* d_in, const int* in_sizes, int n_in,
                              void* d_out, int out_size)
{
    const float* logits  = (const float*)d_in[0];  // [B,N,D]
    const float* head    = (const float*)d_in[1];  // [N,D,C]
    const float* pos_map = (const float*)d_in[2];  // [N,D,D]
    const float* cbw     = (const float*)d_in[3];  // [D,C]
    const float* gum     = (const float*)d_in[4];  // [B,N,C]
    const float* tau     = (const float*)d_in[5];  // [1]

    float* out  = (float*)d_out;
    float* outq = out;                                   // quantized [B,N,D]
    float* la   = out + (size_t)B_ * N_ * D_;            // log_alpha [B,N,C]
    float* z    = la + (size_t)B_ * N_ * C_;             // z [B,N,C]

    k_transpose<<<dim3(C_ / 32, D_ / 32), dim3(32, 8)>>>(cbw);
    k_gemm_head<<<dim3(C_ / 256, N_), 128>>>(logits, head, la);
    k_softmax<<<B_ * N_, 256>>>(la, gum, tau, z);
    k_gemm_cb<<<dim3(64, KSPLIT), 128>>>(z);
    k_posmap<<<N_, 256>>>(pos_map, outq);
}

// round 4
// speedup vs baseline: 1.5597x; 1.3858x over previous
#include <cuda_runtime.h>
#include <cstdint>

typedef unsigned long long u64;

#define B_ 32
#define N_ 64
#define D_ 256
#define C_ 8192
#define KSPLIT 16

// Scratch (static device memory — no runtime allocation).
__device__ float g_q1p[KSPLIT][(size_t)B_ * N_ * D_]; // K-split partials of z@W^T, 32 MB

// ---------- packed f32x2 helpers (posmap epilogue) ----------
__device__ __forceinline__ u64 splat2(float x) {
    u64 r; unsigned xi = __float_as_uint(x);
    asm("mov.b64 %0, {%1, %1};" : "=l"(r) : "r"(xi));
    return r;
}
__device__ __forceinline__ void ffma2(u64 &d, u64 a, u64 b) {
    asm("fma.rn.f32x2 %0, %1, %2, %0;" : "+l"(d) : "l"(a), "l"(b));
}
__device__ __forceinline__ float2 unpack2(u64 v) {
    unsigned lo, hi;
    asm("mov.b64 {%0, %1}, %2;" : "=r"(lo), "=r"(hi) : "l"(v));
    return make_float2(__uint_as_float(lo), __uint_as_float(hi));
}

// ---------- tf32 helpers ----------
__device__ __forceinline__ float tf32_hi(float x) {
    return __uint_as_float(__float_as_uint(x) & 0xFFFFE000u);
}
__device__ __forceinline__ float tf32_rn(float x) {
    unsigned r;
    asm("cvt.rna.tf32.f32 %0, %1;" : "=r"(r) : "f"(x));
    return __uint_as_float(r);
}

// D += A@B, m16n8k8, A row-major, B col-major, tf32 in / fp32 accum
__device__ __forceinline__ void mma8(float* d, const unsigned* a, const unsigned* b) {
    asm volatile(
        "mma.sync.aligned.m16n8k8.row.col.f32.tf32.tf32.f32 "
        "{%0,%1,%2,%3}, {%4,%5,%6,%7}, {%8,%9}, {%0,%1,%2,%3};"
        : "+f"(d[0]), "+f"(d[1]), "+f"(d[2]), "+f"(d[3])
        : "r"(a[0]), "r"(a[1]), "r"(a[2]), "r"(a[3]), "r"(b[0]), "r"(b[1]));
}

// ============ Kernel 1: la[b,n,c] = sum_k logits[b,n,k] * head[n,k,c] ============
// grid (C/256, N), block 256 (8 warps: 2 m-warps x 4 n-warps; warp tile 16x64).
// M=32 (b), N=256 (c slice), K=256, chunks of 32. 3xtf32 split for fp32 accuracy.
// smem: Ah/Al [32][36], Bh/Bl [32][264] (k-major rows of 256 c + pad 8).
#define G1_SMEM_FLOATS (2 * 32 * 36 + 2 * 32 * 264)
__global__ __launch_bounds__(256) void k_gemm_head_mma(
    const float* __restrict__ logits, const float* __restrict__ head,
    float* __restrict__ la)
{
    extern __shared__ __align__(16) float sm1[];
    float* Ah = sm1;
    float* Al = Ah + 32 * 36;
    float* Bh = Al + 32 * 36;
    float* Bl = Bh + 32 * 264;

    const int n  = blockIdx.y;
    const int c0 = blockIdx.x * 256;
    const int tid = threadIdx.x;
    const int wid = tid >> 5, lane = tid & 31;
    const int g = lane >> 2, tig = lane & 3;
    const int wm = wid & 1, wn = wid >> 1;   // wm: 2, wn: 4

    float acc[8][4];
    #pragma unroll
    for (int i = 0; i < 8; i++)
        #pragma unroll
        for (int j = 0; j < 4; j++) acc[i][j] = 0.0f;

    for (int ch = 0; ch < 8; ch++) {
        const int kb = ch * 32;
        __syncthreads();
        // stage A: logits[b][n][kb..kb+32) -> Ah/Al [32][36]
        {
            int r = tid >> 3, q = tid & 7;     // 256 thr -> 32 rows x 8 quads
            float4 v = *reinterpret_cast<const float4*>(
                &logits[((size_t)r * N_ + n) * D_ + kb + 4 * q]);
            float4 h, l;
            h.x = tf32_hi(v.x); l.x = tf32_rn(v.x - h.x);
            h.y = tf32_hi(v.y); l.y = tf32_rn(v.y - h.y);
            h.z = tf32_hi(v.z); l.z = tf32_rn(v.z - h.z);
            h.w = tf32_hi(v.w); l.w = tf32_rn(v.w - h.w);
            *reinterpret_cast<float4*>(&Ah[r * 36 + 4 * q]) = h;
            *reinterpret_cast<float4*>(&Al[r * 36 + 4 * q]) = l;
        }
        // stage B: head[n][kb+k][c0..c0+256) -> Bh/Bl [k][264]
        #pragma unroll
        for (int it = 0; it < 8; it++) {
            int i = tid + it * 256;            // [0, 2048)
            int k = i >> 6, c4 = i & 63;
            float4 v = *reinterpret_cast<const float4*>(
                &head[((size_t)n * D_ + kb + k) * C_ + c0 + 4 * c4]);
            float4 h, l;
            h.x = tf32_hi(v.x); l.x = tf32_rn(v.x - h.x);
            h.y = tf32_hi(v.y); l.y = tf32_rn(v.y - h.y);
            h.z = tf32_hi(v.z); l.z = tf32_rn(v.z - h.z);
            h.w = tf32_hi(v.w); l.w = tf32_rn(v.w - h.w);
            *reinterpret_cast<float4*>(&Bh[k * 264 + 4 * c4]) = h;
            *reinterpret_cast<float4*>(&Bl[k * 264 + 4 * c4]) = l;
        }
        __syncthreads();

        #pragma unroll
        for (int ks = 0; ks < 4; ks++) {
            const int kc = ks * 8 + tig;
            const int row = wm * 16 + g;
            unsigned ah[4], al[4];
            ah[0] = __float_as_uint(Ah[row * 36 + kc]);
            ah[1] = __float_as_uint(Ah[(row + 8) * 36 + kc]);
            ah[2] = __float_as_uint(Ah[row * 36 + kc + 4]);
            ah[3] = __float_as_uint(Ah[(row + 8) * 36 + kc + 4]);
            al[0] = __float_as_uint(Al[row * 36 + kc]);
            al[1] = __float_as_uint(Al[(row + 8) * 36 + kc]);
            al[2] = __float_as_uint(Al[row * 36 + kc + 4]);
            al[3] = __float_as_uint(Al[(row + 8) * 36 + kc + 4]);

            #pragma unroll
            for (int nf = 0; nf < 8; nf++) {
                int c = wn * 64 + nf * 8 + g;
                unsigned bh[2], bl[2];
                bh[0] = __float_as_uint(Bh[kc * 264 + c]);
                bh[1] = __float_as_uint(Bh[(kc + 4) * 264 + c]);
                bl[0] = __float_as_uint(Bl[kc * 264 + c]);
                bl[1] = __float_as_uint(Bl[(kc + 4) * 264 + c]);
                mma8(acc[nf], ah, bh);
                mma8(acc[nf], ah, bl);
                mma8(acc[nf], al, bh);
            }
        }
    }

    // epilogue: la[(b*N + n)*C + c]
    const int r = wm * 16 + g;
    #pragma unroll
    for (int nf = 0; nf < 8; nf++) {
        int c = c0 + wn * 64 + nf * 8 + 2 * tig;
        size_t base = ((size_t)r * N_ + n) * C_ + c;
        *reinterpret_cast<float2*>(&la[base]) = make_float2(acc[nf][0], acc[nf][1]);
        size_t base2 = ((size_t)(r + 8) * N_ + n) * C_ + c;
        *reinterpret_cast<float2*>(&la[base2]) = make_float2(acc[nf][2], acc[nf][3]);
    }
}

// ============ Kernel 2: z = softmax((la + gumbel)/tau) over C ============
__global__ __launch_bounds__(256) void k_softmax(
    const float* __restrict__ la, const float* __restrict__ gum,
    const float* __restrict__ tau, float* __restrict__ z)
{
    __shared__ __align__(16) float sv[C_];
    __shared__ float redm[8];
    __shared__ float reds[8];
    const int m = blockIdx.x;
    const size_t base = (size_t)m * C_;
    const float inv_tau = 1.0f / tau[0];
    const int tid = threadIdx.x;
    const int w = tid >> 5, l = tid & 31;

    float lmax = -3.4e38f;
    for (int c = tid * 4; c < C_; c += 1024) {
        float4 a = *reinterpret_cast<const float4*>(&la[base + c]);
        float4 g = *reinterpret_cast<const float4*>(&gum[base + c]);
        float4 v;
        v.x = (a.x + g.x) * inv_tau;
        v.y = (a.y + g.y) * inv_tau;
        v.z = (a.z + g.z) * inv_tau;
        v.w = (a.w + g.w) * inv_tau;
        *reinterpret_cast<float4*>(&sv[c]) = v;
        lmax = fmaxf(lmax, fmaxf(fmaxf(v.x, v.y), fmaxf(v.z, v.w)));
    }
    #pragma unroll
    for (int off = 16; off; off >>= 1)
        lmax = fmaxf(lmax, __shfl_xor_sync(0xffffffffu, lmax, off));
    if (l == 0) redm[w] = lmax;
    __syncthreads();
    float bmax = redm[0];
    #pragma unroll
    for (int i = 1; i < 8; i++) bmax = fmaxf(bmax, redm[i]);

    float lsum = 0.0f;
    for (int c = tid * 4; c < C_; c += 1024) {
        float4 v = *reinterpret_cast<const float4*>(&sv[c]);
        v.x = __expf(v.x - bmax);
        v.y = __expf(v.y - bmax);
        v.z = __expf(v.z - bmax);
        v.w = __expf(v.w - bmax);
        *reinterpret_cast<float4*>(&sv[c]) = v;
        lsum += (v.x + v.y) + (v.z + v.w);
    }
    #pragma unroll
    for (int off = 16; off; off >>= 1)
        lsum += __shfl_xor_sync(0xffffffffu, lsum, off);
    if (l == 0) reds[w] = lsum;
    __syncthreads();
    float bsum = 0.0f;
    #pragma unroll
    for (int i = 0; i < 8; i++) bsum += reds[i];
    const float inv = 1.0f / bsum;

    for (int c = tid * 4; c < C_; c += 1024) {
        float4 v = *reinterpret_cast<const float4*>(&sv[c]);
        v.x *= inv; v.y *= inv; v.z *= inv; v.w *= inv;
        *reinterpret_cast<float4*>(&z[base + c]) = v;
    }
}

// ============ Kernel 3: q1[m,d] = sum_c z[m,c] * W[d,c], 16 K-split partials ============
// grid (16 m-tiles, 16 k-splits), block 512 (16 warps: 2 m x 8 n; warp tile 64x32).
// CTA tile 128(M) x 256(N=D), K-slice 512 in chunks of 32. 3xtf32.
// smem: Ah/Al [128][36], Bh/Bl [256][36].
#define G2_SMEM_FLOATS (2 * 128 * 36 + 2 * 256 * 36)
__global__ __launch_bounds__(512) void k_gemm_cb_mma(
    const float* __restrict__ z, const float* __restrict__ W)
{
    extern __shared__ __align__(16) float sm2[];
    float* Ah = sm2;
    float* Al = Ah + 128 * 36;
    float* Bh = Al + 128 * 36;
    float* Bl = Bh + 256 * 36;

    const int m0 = blockIdx.x * 128;
    const int k0 = blockIdx.y * 512;
    float* part = g_q1p[blockIdx.y];
    const int tid = threadIdx.x;
    const int wid = tid >> 5, lane = tid & 31;
    const int g = lane >> 2, tig = lane & 3;
    const int wm = wid & 1, wn = wid >> 1;   // wm: 2, wn: 8

    float acc[4][4][4];
    #pragma unroll
    for (int i = 0; i < 4; i++)
        #pragma unroll
        for (int j = 0; j < 4; j++)
            #pragma unroll
            for (int t = 0; t < 4; t++) acc[i][j][t] = 0.0f;

    for (int ch = 0; ch < 16; ch++) {
        const int kb = k0 + ch * 32;
        __syncthreads();
        // stage A: z[m0+r][kb..kb+32)
        #pragma unroll
        for (int it = 0; it < 2; it++) {
            int i = tid + it * 512;            // [0, 1024)
            int r = i >> 3, q = i & 7;
            float4 v = *reinterpret_cast<const float4*>(
                &z[(size_t)(m0 + r) * C_ + kb + 4 * q]);
            float4 h, l;
            h.x = tf32_hi(v.x); l.x = tf32_rn(v.x - h.x);
            h.y = tf32_hi(v.y); l.y = tf32_rn(v.y - h.y);
            h.z = tf32_hi(v.z); l.z = tf32_rn(v.z - h.z);
            h.w = tf32_hi(v.w); l.w = tf32_rn(v.w - h.w);
            *reinterpret_cast<float4*>(&Ah[r * 36 + 4 * q]) = h;
            *reinterpret_cast<float4*>(&Al[r * 36 + 4 * q]) = l;
        }
        // stage B: W[d][kb..kb+32) for all 256 d
        #pragma unroll
        for (int it = 0; it < 4; it++) {
            int i = tid + it * 512;            // [0, 2048)
            int r = i >> 3, q = i & 7;
            float4 v = *reinterpret_cast<const float4*>(
                &W[(size_t)r * C_ + kb + 4 * q]);
            float4 h, l;
            h.x = tf32_hi(v.x); l.x = tf32_rn(v.x - h.x);
            h.y = tf32_hi(v.y); l.y = tf32_rn(v.y - h.y);
            h.z = tf32_hi(v.z); l.z = tf32_rn(v.z - h.z);
            h.w = tf32_hi(v.w); l.w = tf32_rn(v.w - h.w);
            *reinterpret_cast<float4*>(&Bh[r * 36 + 4 * q]) = h;
            *reinterpret_cast<float4*>(&Bl[r * 36 + 4 * q]) = l;
        }
        __syncthreads();

        #pragma unroll
        for (int ks = 0; ks < 4; ks++) {
            const int kc = ks * 8 + tig;
            unsigned bh[4][2], bl[4][2];
            #pragma unroll
            for (int nf = 0; nf < 4; nf++) {
                int nn = wn * 32 + nf * 8 + g;
                bh[nf][0] = __float_as_uint(Bh[nn * 36 + kc]);
                bh[nf][1] = __float_as_uint(Bh[nn * 36 + kc + 4]);
                bl[nf][0] = __float_as_uint(Bl[nn * 36 + kc]);
                bl[nf][1] = __float_as_uint(Bl[nn * 36 + kc + 4]);
            }
            #pragma unroll
            for (int mf = 0; mf < 4; mf++) {
                int row = wm * 64 + mf * 16 + g;
                unsigned ah[4], al[4];
                ah[0] = __float_as_uint(Ah[row * 36 + kc]);
                ah[1] = __float_as_uint(Ah[(row + 8) * 36 + kc]);
                ah[2] = __float_as_uint(Ah[row * 36 + kc + 4]);
                ah[3] = __float_as_uint(Ah[(row + 8) * 36 + kc + 4]);
                al[0] = __float_as_uint(Al[row * 36 + kc]);
                al[1] = __float_as_uint(Al[(row + 8) * 36 + kc]);
                al[2] = __float_as_uint(Al[row * 36 + kc + 4]);
                al[3] = __float_as_uint(Al[(row + 8) * 36 + kc + 4]);
                #pragma unroll
                for (int nf = 0; nf < 4; nf++) {
                    mma8(acc[mf][nf], ah, bh[nf]);
                    mma8(acc[mf][nf], ah, bl[nf]);
                    mma8(acc[mf][nf], al, bh[nf]);
                }
            }
        }
    }

    // epilogue
    #pragma unroll
    for (int mf = 0; mf < 4; mf++) {
        int r = m0 + wm * 64 + mf * 16 + g;
        #pragma unroll
        for (int nf = 0; nf < 4; nf++) {
            int d = wn * 32 + nf * 8 + 2 * tig;
            *reinterpret_cast<float2*>(&part[(size_t)r * D_ + d]) =
                make_float2(acc[mf][nf][0], acc[mf][nf][1]);
            *reinterpret_cast<float2*>(&part[(size_t)(r + 8) * D_ + d]) =
                make_float2(acc[mf][nf][2], acc[mf][nf][3]);
        }
    }
}

// ============ Kernel 4: quantized[b,n,j] = sum_d q1[b,n,d] * pos_map[n,d,j] ============
__global__ __launch_bounds__(256) void k_posmap(
    const float* __restrict__ pm, float* __restrict__ outq)
{
    __shared__ __align__(16) float qs[256 * 36];
    const int n = blockIdx.x;
    const int tid = threadIdx.x;

    for (int i = tid; i < 32 * 256; i += 256) {
        int b = i >> 8, dd = i & 255;
        size_t idx = ((size_t)b * N_ + n) * D_ + dd;
        float s = 0.0f;
        #pragma unroll
        for (int p = 0; p < KSPLIT; p++) s += g_q1p[p][idx];
        qs[dd * 36 + b] = s;
    }
    __syncthreads();

    const int jg = tid & 127, rg = tid >> 7;
    const int j  = jg * 2, r0 = rg * 16;

    u64 acc[8][2];
    #pragma unroll
    for (int p = 0; p < 8; p++) { acc[p][0] = 0ull; acc[p][1] = 0ull; }

    #pragma unroll 4
    for (int dd = 0; dd < 256; dd++) {
        float2 wv = *reinterpret_cast<const float2*>(&pm[((size_t)n * D_ + dd) * D_ + j]);
        u64 w0 = splat2(wv.x), w1 = splat2(wv.y);
        const u64* ap = reinterpret_cast<const u64*>(&qs[dd * 36 + r0]);
        #pragma unroll
        for (int p = 0; p < 8; p++) {
            u64 a2 = ap[p];
            ffma2(acc[p][0], a2, w0);
            ffma2(acc[p][1], a2, w1);
        }
    }

    #pragma unroll
    for (int p = 0; p < 8; p++) {
        float2 v0 = unpack2(acc[p][0]);
        float2 v1 = unpack2(acc[p][1]);
        int rlo = r0 + 2 * p;
        float2 lo = make_float2(v0.x, v1.x);
        float2 hi = make_float2(v0.y, v1.y);
        *reinterpret_cast<float2*>(&outq[((size_t)rlo * N_ + n) * D_ + j]) = lo;
        *reinterpret_cast<float2*>(&outq[((size_t)(rlo + 1) * N_ + n) * D_ + j]) = hi;
    }
}

extern "C" void kernel_launch(void* const* d_in, const int* in_sizes, int n_in,
                              void* d_out, int out_size)
{
    const float* logits  = (const float*)d_in[0];  // [B,N,D]
    const float* head    = (const float*)d_in[1];  // [N,D,C]
    const float* pos_map = (const float*)d_in[2];  // [N,D,D]
    const float* cbw     = (const float*)d_in[3];  // [D,C]
    const float* gum     = (const float*)d_in[4];  // [B,N,C]
    const float* tau     = (const float*)d_in[5];  // [1]

    float* out  = (float*)d_out;
    float* outq = out;                                   // quantized [B,N,D]
    float* la   = out + (size_t)B_ * N_ * D_;            // log_alpha [B,N,C]
    float* z    = la + (size_t)B_ * N_ * C_;             // z [B,N,C]

    const int g1_smem = G1_SMEM_FLOATS * 4;   // 76800 B
    const int g2_smem = G2_SMEM_FLOATS * 4;   // 110592 B
    cudaFuncSetAttribute(k_gemm_head_mma, cudaFuncAttributeMaxDynamicSharedMemorySize, g1_smem);
    cudaFuncSetAttribute(k_gemm_cb_mma,  cudaFuncAttributeMaxDynamicSharedMemorySize, g2_smem);

    k_gemm_head_mma<<<dim3(C_ / 256, N_), 256, g1_smem>>>(logits, head, la);
    k_softmax<<<B_ * N_, 256>>>(la, gum, tau, z);
    k_gemm_cb_mma<<<dim3(16, KSPLIT), 512, g2_smem>>>(z, cbw);
    k_posmap<<<N_, 256>>>(pos_map, outq);
}

// round 5
// speedup vs baseline: 1.6347x; 1.0481x over previous
#include <cuda_runtime.h>
#include <cstdint>

typedef unsigned long long u64;

#define B_ 32
#define N_ 64
#define D_ 256
#define C_ 8192
#define KSPLIT 16

// Scratch (static device memory — no runtime allocation).
__device__ float g_q1p[KSPLIT][(size_t)B_ * N_ * D_]; // K-split partials, 32 MB
__device__ float g_q1[(size_t)B_ * N_ * D_];          // reduced q1, 2 MB
__device__ float g_v[(size_t)B_ * N_ * C_];           // (la+gum)/tau scratch, 64 MB

// ---------- packed f32x2 helpers ----------
__device__ __forceinline__ u64 splat2(float x) {
    u64 r; unsigned xi = __float_as_uint(x);
    asm("mov.b64 %0, {%1, %1};" : "=l"(r) : "r"(xi));
    return r;
}
__device__ __forceinline__ void ffma2(u64 &d, u64 a, u64 b) {
    asm("fma.rn.f32x2 %0, %1, %2, %0;" : "+l"(d) : "l"(a), "l"(b));
}
__device__ __forceinline__ float2 unpack2(u64 v) {
    unsigned lo, hi;
    asm("mov.b64 {%0, %1}, %2;" : "=r"(lo), "=r"(hi) : "l"(v));
    return make_float2(__uint_as_float(lo), __uint_as_float(hi));
}

// ---------- tf32 helpers ----------
__device__ __forceinline__ float tf32_hi(float x) {
    return __uint_as_float(__float_as_uint(x) & 0xFFFFE000u);
}
__device__ __forceinline__ float tf32_rn(float x) {
    unsigned r;
    asm("cvt.rna.tf32.f32 %0, %1;" : "=r"(r) : "f"(x));
    return __uint_as_float(r);
}
__device__ __forceinline__ void split4(float4 v, float4 &h, float4 &l) {
    h.x = tf32_hi(v.x); l.x = tf32_rn(v.x - h.x);
    h.y = tf32_hi(v.y); l.y = tf32_rn(v.y - h.y);
    h.z = tf32_hi(v.z); l.z = tf32_rn(v.z - h.z);
    h.w = tf32_hi(v.w); l.w = tf32_rn(v.w - h.w);
}

// D += A@B, m16n8k8, A row-major, B col-major, tf32 in / fp32 accum
__device__ __forceinline__ void mma8(float* d, const unsigned* a, const unsigned* b) {
    asm volatile(
        "mma.sync.aligned.m16n8k8.row.col.f32.tf32.tf32.f32 "
        "{%0,%1,%2,%3}, {%4,%5,%6,%7}, {%8,%9}, {%0,%1,%2,%3};"
        : "+f"(d[0]), "+f"(d[1]), "+f"(d[2]), "+f"(d[3])
        : "r"(a[0]), "r"(a[1]), "r"(a[2]), "r"(a[3]), "r"(b[0]), "r"(b[1]));
}

// ============ Kernel 1: la[b,n,c] = sum_k logits[b,n,k] * head[n,k,c] ============
// grid (C/256, N), block 256 (8 warps: 2m x 4n; warp tile 16x64). K=256, chunks of 32.
// Register-prefetch double buffering; fused epilogue writes la AND v=(la+gum)/tau.
#define G1_SMEM_FLOATS (2 * 32 * 36 + 2 * 32 * 264)
__global__ __launch_bounds__(256, 2) void k_gemm_head_mma(
    const float* __restrict__ logits, const float* __restrict__ head,
    const float* __restrict__ gum, const float* __restrict__ tau,
    float* __restrict__ la)
{
    extern __shared__ __align__(16) float sm1[];
    float* Ah = sm1;
    float* Al = Ah + 32 * 36;
    float* Bh = Al + 32 * 36;
    float* Bl = Bh + 32 * 264;

    const int n  = blockIdx.y;
    const int c0 = blockIdx.x * 256;
    const int tid = threadIdx.x;
    const int wid = tid >> 5, lane = tid & 31;
    const int g = lane >> 2, tig = lane & 3;
    const int wm = wid & 1, wn = wid >> 1;

    // staging indices
    const int ra = tid >> 3, qa = tid & 7;  // A: 1 float4 per thread

    float acc[8][4];
    #pragma unroll
    for (int i = 0; i < 8; i++)
        #pragma unroll
        for (int j = 0; j < 4; j++) acc[i][j] = 0.0f;

    // prologue: load + stage chunk 0
    {
        float4 va = *reinterpret_cast<const float4*>(
            &logits[((size_t)ra * N_ + n) * D_ + 4 * qa]);
        float4 vb[8];
        #pragma unroll
        for (int it = 0; it < 8; it++) {
            int i = tid + it * 256;
            int k = i >> 6, c4 = i & 63;
            vb[it] = *reinterpret_cast<const float4*>(
                &head[((size_t)n * D_ + k) * C_ + c0 + 4 * c4]);
        }
        float4 h, l;
        split4(va, h, l);
        *reinterpret_cast<float4*>(&Ah[ra * 36 + 4 * qa]) = h;
        *reinterpret_cast<float4*>(&Al[ra * 36 + 4 * qa]) = l;
        #pragma unroll
        for (int it = 0; it < 8; it++) {
            int i = tid + it * 256;
            int k = i >> 6, c4 = i & 63;
            split4(vb[it], h, l);
            *reinterpret_cast<float4*>(&Bh[k * 264 + 4 * c4]) = h;
            *reinterpret_cast<float4*>(&Bl[k * 264 + 4 * c4]) = l;
        }
    }
    __syncthreads();

    for (int ch = 0; ch < 8; ch++) {
        float4 na; float4 nb[8];
        if (ch < 7) {
            const int kb = (ch + 1) * 32;
            na = *reinterpret_cast<const float4*>(
                &logits[((size_t)ra * N_ + n) * D_ + kb + 4 * qa]);
            #pragma unroll
            for (int it = 0; it < 8; it++) {
                int i = tid + it * 256;
                int k = i >> 6, c4 = i & 63;
                nb[it] = *reinterpret_cast<const float4*>(
                    &head[((size_t)n * D_ + kb + k) * C_ + c0 + 4 * c4]);
            }
        }

        // compute on staged chunk
        #pragma unroll
        for (int ks = 0; ks < 4; ks++) {
            const int kc = ks * 8 + tig;
            const int row = wm * 16 + g;
            unsigned ah[4], al[4];
            ah[0] = __float_as_uint(Ah[row * 36 + kc]);
            ah[1] = __float_as_uint(Ah[(row + 8) * 36 + kc]);
            ah[2] = __float_as_uint(Ah[row * 36 + kc + 4]);
            ah[3] = __float_as_uint(Ah[(row + 8) * 36 + kc + 4]);
            al[0] = __float_as_uint(Al[row * 36 + kc]);
            al[1] = __float_as_uint(Al[(row + 8) * 36 + kc]);
            al[2] = __float_as_uint(Al[row * 36 + kc + 4]);
            al[3] = __float_as_uint(Al[(row + 8) * 36 + kc + 4]);

            #pragma unroll
            for (int nf = 0; nf < 8; nf++) {
                int c = wn * 64 + nf * 8 + g;
                unsigned bh[2], bl[2];
                bh[0] = __float_as_uint(Bh[kc * 264 + c]);
                bh[1] = __float_as_uint(Bh[(kc + 4) * 264 + c]);
                bl[0] = __float_as_uint(Bl[kc * 264 + c]);
                bl[1] = __float_as_uint(Bl[(kc + 4) * 264 + c]);
                mma8(acc[nf], ah, bh);
                mma8(acc[nf], ah, bl);
                mma8(acc[nf], al, bh);
            }
        }
        __syncthreads();

        if (ch < 7) {
            float4 h, l;
            split4(na, h, l);
            *reinterpret_cast<float4*>(&Ah[ra * 36 + 4 * qa]) = h;
            *reinterpret_cast<float4*>(&Al[ra * 36 + 4 * qa]) = l;
            #pragma unroll
            for (int it = 0; it < 8; it++) {
                int i = tid + it * 256;
                int k = i >> 6, c4 = i & 63;
                split4(nb[it], h, l);
                *reinterpret_cast<float4*>(&Bh[k * 264 + 4 * c4]) = h;
                *reinterpret_cast<float4*>(&Bl[k * 264 + 4 * c4]) = l;
            }
            __syncthreads();
        }
    }

    // fused epilogue: write la and v = (la + gum) / tau
    const float inv_tau = 1.0f / tau[0];
    const int r = wm * 16 + g;
    #pragma unroll
    for (int nf = 0; nf < 8; nf++) {
        int c = c0 + wn * 64 + nf * 8 + 2 * tig;
        size_t b1 = ((size_t)r * N_ + n) * C_ + c;
        size_t b2 = ((size_t)(r + 8) * N_ + n) * C_ + c;
        float2 l1 = make_float2(acc[nf][0], acc[nf][1]);
        float2 l2 = make_float2(acc[nf][2], acc[nf][3]);
        *reinterpret_cast<float2*>(&la[b1]) = l1;
        *reinterpret_cast<float2*>(&la[b2]) = l2;
        float2 g1 = *reinterpret_cast<const float2*>(&gum[b1]);
        float2 g2 = *reinterpret_cast<const float2*>(&gum[b2]);
        *reinterpret_cast<float2*>(&g_v[b1]) =
            make_float2((l1.x + g1.x) * inv_tau, (l1.y + g1.y) * inv_tau);
        *reinterpret_cast<float2*>(&g_v[b2]) =
            make_float2((l2.x + g2.x) * inv_tau, (l2.y + g2.y) * inv_tau);
    }
}

// ============ Kernel 2: z = softmax(v) over C (v precomputed) ============
__global__ __launch_bounds__(256) void k_softmax(float* __restrict__ z)
{
    __shared__ __align__(16) float sv[C_];
    __shared__ float redm[8];
    __shared__ float reds[8];
    const int m = blockIdx.x;
    const size_t base = (size_t)m * C_;
    const int tid = threadIdx.x;
    const int w = tid >> 5, l = tid & 31;

    float lmax = -3.4e38f;
    for (int c = tid * 4; c < C_; c += 1024) {
        float4 v = *reinterpret_cast<const float4*>(&g_v[base + c]);
        *reinterpret_cast<float4*>(&sv[c]) = v;
        lmax = fmaxf(lmax, fmaxf(fmaxf(v.x, v.y), fmaxf(v.z, v.w)));
    }
    #pragma unroll
    for (int off = 16; off; off >>= 1)
        lmax = fmaxf(lmax, __shfl_xor_sync(0xffffffffu, lmax, off));
    if (l == 0) redm[w] = lmax;
    __syncthreads();
    float bmax = redm[0];
    #pragma unroll
    for (int i = 1; i < 8; i++) bmax = fmaxf(bmax, redm[i]);

    float lsum = 0.0f;
    for (int c = tid * 4; c < C_; c += 1024) {
        float4 v = *reinterpret_cast<const float4*>(&sv[c]);
        v.x = __expf(v.x - bmax);
        v.y = __expf(v.y - bmax);
        v.z = __expf(v.z - bmax);
        v.w = __expf(v.w - bmax);
        *reinterpret_cast<float4*>(&sv[c]) = v;
        lsum += (v.x + v.y) + (v.z + v.w);
    }
    #pragma unroll
    for (int off = 16; off; off >>= 1)
        lsum += __shfl_xor_sync(0xffffffffu, lsum, off);
    if (l == 0) reds[w] = lsum;
    __syncthreads();
    float bsum = 0.0f;
    #pragma unroll
    for (int i = 0; i < 8; i++) bsum += reds[i];
    const float inv = 1.0f / bsum;

    for (int c = tid * 4; c < C_; c += 1024) {
        float4 v = *reinterpret_cast<const float4*>(&sv[c]);
        v.x *= inv; v.y *= inv; v.z *= inv; v.w *= inv;
        *reinterpret_cast<float4*>(&z[base + c]) = v;
    }
}

// ============ Kernel 3: q1 partials = z @ W^T (16 K-splits) ============
// grid (16 m-tiles, 16 k-splits), block 512 (16 warps: 2m x 8n; warp 64x32).
// Register-prefetch double buffering.
#define G2_SMEM_FLOATS (2 * 128 * 36 + 2 * 256 * 36)
__global__ __launch_bounds__(512) void k_gemm_cb_mma(
    const float* __restrict__ z, const float* __restrict__ W)
{
    extern __shared__ __align__(16) float sm2[];
    float* Ah = sm2;
    float* Al = Ah + 128 * 36;
    float* Bh = Al + 128 * 36;
    float* Bl = Bh + 256 * 36;

    const int m0 = blockIdx.x * 128;
    const int k0 = blockIdx.y * 512;
    float* part = g_q1p[blockIdx.y];
    const int tid = threadIdx.x;
    const int wid = tid >> 5, lane = tid & 31;
    const int g = lane >> 2, tig = lane & 3;
    const int wm = wid & 1, wn = wid >> 1;

    float acc[4][4][4];
    #pragma unroll
    for (int i = 0; i < 4; i++)
        #pragma unroll
        for (int j = 0; j < 4; j++)
            #pragma unroll
            for (int t = 0; t < 4; t++) acc[i][j][t] = 0.0f;

    // prologue: stage chunk 0
    {
        float4 va[2], vb[4];
        #pragma unroll
        for (int it = 0; it < 2; it++) {
            int i = tid + it * 512;
            int r = i >> 3, q = i & 7;
            va[it] = *reinterpret_cast<const float4*>(
                &z[(size_t)(m0 + r) * C_ + k0 + 4 * q]);
        }
        #pragma unroll
        for (int it = 0; it < 4; it++) {
            int i = tid + it * 512;
            int r = i >> 3, q = i & 7;
            vb[it] = *reinterpret_cast<const float4*>(
                &W[(size_t)r * C_ + k0 + 4 * q]);
        }
        float4 h, l;
        #pragma unroll
        for (int it = 0; it < 2; it++) {
            int i = tid + it * 512;
            int r = i >> 3, q = i & 7;
            split4(va[it], h, l);
            *reinterpret_cast<float4*>(&Ah[r * 36 + 4 * q]) = h;
            *reinterpret_cast<float4*>(&Al[r * 36 + 4 * q]) = l;
        }
        #pragma unroll
        for (int it = 0; it < 4; it++) {
            int i = tid + it * 512;
            int r = i >> 3, q = i & 7;
            split4(vb[it], h, l);
            *reinterpret_cast<float4*>(&Bh[r * 36 + 4 * q]) = h;
            *reinterpret_cast<float4*>(&Bl[r * 36 + 4 * q]) = l;
        }
    }
    __syncthreads();

    for (int ch = 0; ch < 16; ch++) {
        float4 na[2], nb[4];
        if (ch < 15) {
            const int kb = k0 + (ch + 1) * 32;
            #pragma unroll
            for (int it = 0; it < 2; it++) {
                int i = tid + it * 512;
                int r = i >> 3, q = i & 7;
                na[it] = *reinterpret_cast<const float4*>(
                    &z[(size_t)(m0 + r) * C_ + kb + 4 * q]);
            }
            #pragma unroll
            for (int it = 0; it < 4; it++) {
                int i = tid + it * 512;
                int r = i >> 3, q = i & 7;
                nb[it] = *reinterpret_cast<const float4*>(
                    &W[(size_t)r * C_ + kb + 4 * q]);
            }
        }

        #pragma unroll
        for (int ks = 0; ks < 4; ks++) {
            const int kc = ks * 8 + tig;
            unsigned bh[4][2], bl[4][2];
            #pragma unroll
            for (int nf = 0; nf < 4; nf++) {
                int nn = wn * 32 + nf * 8 + g;
                bh[nf][0] = __float_as_uint(Bh[nn * 36 + kc]);
                bh[nf][1] = __float_as_uint(Bh[nn * 36 + kc + 4]);
                bl[nf][0] = __float_as_uint(Bl[nn * 36 + kc]);
                bl[nf][1] = __float_as_uint(Bl[nn * 36 + kc + 4]);
            }
            #pragma unroll
            for (int mf = 0; mf < 4; mf++) {
                int row = wm * 64 + mf * 16 + g;
                unsigned ah[4], al[4];
                ah[0] = __float_as_uint(Ah[row * 36 + kc]);
                ah[1] = __float_as_uint(Ah[(row + 8) * 36 + kc]);
                ah[2] = __float_as_uint(Ah[row * 36 + kc + 4]);
                ah[3] = __float_as_uint(Ah[(row + 8) * 36 + kc + 4]);
                al[0] = __float_as_uint(Al[row * 36 + kc]);
                al[1] = __float_as_uint(Al[(row + 8) * 36 + kc]);
                al[2] = __float_as_uint(Al[row * 36 + kc + 4]);
                al[3] = __float_as_uint(Al[(row + 8) * 36 + kc + 4]);
                #pragma unroll
                for (int nf = 0; nf < 4; nf++) {
                    mma8(acc[mf][nf], ah, bh[nf]);
                    mma8(acc[mf][nf], ah, bl[nf]);
                    mma8(acc[mf][nf], al, bh[nf]);
                }
            }
        }
        __syncthreads();

        if (ch < 15) {
            float4 h, l;
            #pragma unroll
            for (int it = 0; it < 2; it++) {
                int i = tid + it * 512;
                int r = i >> 3, q = i & 7;
                split4(na[it], h, l);
                *reinterpret_cast<float4*>(&Ah[r * 36 + 4 * q]) = h;
                *reinterpret_cast<float4*>(&Al[r * 36 + 4 * q]) = l;
            }
            #pragma unroll
            for (int it = 0; it < 4; it++) {
                int i = tid + it * 512;
                int r = i >> 3, q = i & 7;
                split4(nb[it], h, l);
                *reinterpret_cast<float4*>(&Bh[r * 36 + 4 * q]) = h;
                *reinterpret_cast<float4*>(&Bl[r * 36 + 4 * q]) = l;
            }
            __syncthreads();
        }
    }

    #pragma unroll
    for (int mf = 0; mf < 4; mf++) {
        int r = m0 + wm * 64 + mf * 16 + g;
        #pragma unroll
        for (int nf = 0; nf < 4; nf++) {
            int d = wn * 32 + nf * 8 + 2 * tig;
            *reinterpret_cast<float2*>(&part[(size_t)r * D_ + d]) =
                make_float2(acc[mf][nf][0], acc[mf][nf][1]);
            *reinterpret_cast<float2*>(&part[(size_t)(r + 8) * D_ + d]) =
                make_float2(acc[mf][nf][2], acc[mf][nf][3]);
        }
    }
}

// ============ Kernel 4: q1 = sum of 16 partials ============
__global__ __launch_bounds__(256) void k_reduce()
{
    size_t i = ((size_t)blockIdx.x * 256 + threadIdx.x) * 4;
    float4 s = *reinterpret_cast<const float4*>(&g_q1p[0][i]);
    #pragma unroll
    for (int p = 1; p < KSPLIT; p++) {
        float4 v = *reinterpret_cast<const float4*>(&g_q1p[p][i]);
        s.x += v.x; s.y += v.y; s.z += v.z; s.w += v.w;
    }
    *reinterpret_cast<float4*>(&g_q1[i]) = s;
}

// ============ Kernel 5: quantized[b,n,j] = sum_d q1[b,n,d] * pos_map[n,d,j] ============
// grid (64 n, 4 j-splits), block 256.
__global__ __launch_bounds__(256) void k_posmap(
    const float* __restrict__ pm, float* __restrict__ outq)
{
    __shared__ __align__(16) float qs[256 * 36];
    const int n = blockIdx.x;
    const int j0 = blockIdx.y * 64;
    const int tid = threadIdx.x;

    for (int i = tid; i < 32 * 256; i += 256) {
        int b = i >> 8, dd = i & 255;
        qs[dd * 36 + b] = g_q1[((size_t)b * N_ + n) * D_ + dd];
    }
    __syncthreads();

    const int jg = tid & 31, rg = tid >> 5;
    const int j  = j0 + jg * 2, r0 = rg * 4;

    u64 acc[2][2];
    acc[0][0] = acc[0][1] = acc[1][0] = acc[1][1] = 0ull;

    #pragma unroll 4
    for (int dd = 0; dd < 256; dd++) {
        float2 wv = *reinterpret_cast<const float2*>(&pm[((size_t)n * D_ + dd) * D_ + j]);
        u64 w0 = splat2(wv.x), w1 = splat2(wv.y);
        const u64* ap = reinterpret_cast<const u64*>(&qs[dd * 36 + r0]);
        u64 a0 = ap[0], a1 = ap[1];
        ffma2(acc[0][0], a0, w0);
        ffma2(acc[0][1], a0, w1);
        ffma2(acc[1][0], a1, w0);
        ffma2(acc[1][1], a1, w1);
    }

    #pragma unroll
    for (int p = 0; p < 2; p++) {
        float2 v0 = unpack2(acc[p][0]);
        float2 v1 = unpack2(acc[p][1]);
        int rlo = r0 + 2 * p;
        *reinterpret_cast<float2*>(&outq[((size_t)rlo * N_ + n) * D_ + j]) =
            make_float2(v0.x, v1.x);
        *reinterpret_cast<float2*>(&outq[((size_t)(rlo + 1) * N_ + n) * D_ + j]) =
            make_float2(v0.y, v1.y);
    }
}

extern "C" void kernel_launch(void* const* d_in, const int* in_sizes, int n_in,
                              void* d_out, int out_size)
{
    const float* logits  = (const float*)d_in[0];  // [B,N,D]
    const float* head    = (const float*)d_in[1];  // [N,D,C]
    const float* pos_map = (const float*)d_in[2];  // [N,D,D]
    const float* cbw     = (const float*)d_in[3];  // [D,C]
    const float* gum     = (const float*)d_in[4];  // [B,N,C]
    const float* tau     = (const float*)d_in[5];  // [1]

    float* out  = (float*)d_out;
    float* outq = out;                                   // quantized [B,N,D]
    float* la   = out + (size_t)B_ * N_ * D_;            // log_alpha [B,N,C]
    float* z    = la + (size_t)B_ * N_ * C_;             // z [B,N,C]

    const int g1_smem = G1_SMEM_FLOATS * 4;   // 76800 B
    const int g2_smem = G2_SMEM_FLOATS * 4;   // 110592 B
    cudaFuncSetAttribute(k_gemm_head_mma, cudaFuncAttributeMaxDynamicSharedMemorySize, g1_smem);
    cudaFuncSetAttribute(k_gemm_cb_mma,  cudaFuncAttributeMaxDynamicSharedMemorySize, g2_smem);

    k_gemm_head_mma<<<dim3(C_ / 256, N_), 256, g1_smem>>>(logits, head, gum, tau, la);
    k_softmax<<<B_ * N_, 256>>>(z);
    k_gemm_cb_mma<<<dim3(16, KSPLIT), 512, g2_smem>>>(z, cbw);
    k_reduce<<<(B_ * N_ * D_) / (256 * 4), 256>>>();
    k_posmap<<<dim3(N_, 4), 256>>>(pos_map, outq);
}

// round 6
// speedup vs baseline: 2.0227x; 1.2374x over previous
#include <cuda_runtime.h>
#include <cuda_bf16.h>
#include <cstdint>

typedef unsigned long long u64;

#define B_ 32
#define N_ 64
#define D_ 256
#define C_ 8192
#define KSPLIT 8

// Scratch (static device memory — no runtime allocation).
__device__ float g_q1p[KSPLIT][(size_t)B_ * N_ * D_]; // K-split partials, 16 MB
__device__ float g_q1[(size_t)B_ * N_ * D_];          // reduced q1, 2 MB
__device__ float g_v[(size_t)B_ * N_ * C_];           // (la+gum)/tau scratch, 64 MB

// ---------- packed f32x2 helpers ----------
__device__ __forceinline__ u64 splat2(float x) {
    u64 r; unsigned xi = __float_as_uint(x);
    asm("mov.b64 %0, {%1, %1};" : "=l"(r) : "r"(xi));
    return r;
}
__device__ __forceinline__ void ffma2(u64 &d, u64 a, u64 b) {
    asm("fma.rn.f32x2 %0, %1, %2, %0;" : "+l"(d) : "l"(a), "l"(b));
}
__device__ __forceinline__ float2 unpack2(u64 v) {
    unsigned lo, hi;
    asm("mov.b64 {%0, %1}, %2;" : "=r"(lo), "=r"(hi) : "l"(v));
    return make_float2(__uint_as_float(lo), __uint_as_float(hi));
}

// ---------- tf32 helpers (GEMM1) ----------
__device__ __forceinline__ float tf32_hi(float x) {
    return __uint_as_float(__float_as_uint(x) & 0xFFFFE000u);
}
__device__ __forceinline__ float tf32_rn(float x) {
    unsigned r;
    asm("cvt.rna.tf32.f32 %0, %1;" : "=r"(r) : "f"(x));
    return __uint_as_float(r);
}
__device__ __forceinline__ void split4(float4 v, float4 &h, float4 &l) {
    h.x = tf32_hi(v.x); l.x = tf32_rn(v.x - h.x);
    h.y = tf32_hi(v.y); l.y = tf32_rn(v.y - h.y);
    h.z = tf32_hi(v.z); l.z = tf32_rn(v.z - h.z);
    h.w = tf32_hi(v.w); l.w = tf32_rn(v.w - h.w);
}

// ---------- bf16 split (GEMM2): (x,y) -> packed hi bf16x2 + packed lo bf16x2 ----------
__device__ __forceinline__ void bsplit2(float x, float y, unsigned &h, unsigned &l) {
    unsigned hp;
    asm("cvt.rn.bf16x2.f32 %0, %1, %2;" : "=r"(hp) : "f"(y), "f"(x));
    float hx = __uint_as_float(hp << 16);
    float hy = __uint_as_float(hp & 0xFFFF0000u);
    asm("cvt.rn.bf16x2.f32 %0, %1, %2;" : "=r"(l) : "f"(y - hy), "f"(x - hx));
    h = hp;
}

// D += A@B, m16n8k8 tf32
__device__ __forceinline__ void mma8(float* d, const unsigned* a, const unsigned* b) {
    asm volatile(
        "mma.sync.aligned.m16n8k8.row.col.f32.tf32.tf32.f32 "
        "{%0,%1,%2,%3}, {%4,%5,%6,%7}, {%8,%9}, {%0,%1,%2,%3};"
        : "+f"(d[0]), "+f"(d[1]), "+f"(d[2]), "+f"(d[3])
        : "r"(a[0]), "r"(a[1]), "r"(a[2]), "r"(a[3]), "r"(b[0]), "r"(b[1]));
}
// D += A@B, m16n8k16 bf16
__device__ __forceinline__ void mma16(float* d, const unsigned* a, const unsigned* b) {
    asm volatile(
        "mma.sync.aligned.m16n8k16.row.col.f32.bf16.bf16.f32 "
        "{%0,%1,%2,%3}, {%4,%5,%6,%7}, {%8,%9}, {%0,%1,%2,%3};"
        : "+f"(d[0]), "+f"(d[1]), "+f"(d[2]), "+f"(d[3])
        : "r"(a[0]), "r"(a[1]), "r"(a[2]), "r"(a[3]), "r"(b[0]), "r"(b[1]));
}

// ============ Kernel 1: la[b,n,c] = sum_k logits[b,n,k] * head[n,k,c] ============
// grid (C/256, N), block 256 (8 warps: 2m x 4n; warp tile 16x64). 3xtf32 split.
// Register-prefetch double buffering; fused epilogue writes la AND v=(la+gum)/tau.
#define G1_SMEM_FLOATS (2 * 32 * 36 + 2 * 32 * 264)
__global__ __launch_bounds__(256, 2) void k_gemm_head_mma(
    const float* __restrict__ logits, const float* __restrict__ head,
    const float* __restrict__ gum, const float* __restrict__ tau,
    float* __restrict__ la)
{
    extern __shared__ __align__(16) float sm1[];
    float* Ah = sm1;
    float* Al = Ah + 32 * 36;
    float* Bh = Al + 32 * 36;
    float* Bl = Bh + 32 * 264;

    const int n  = blockIdx.y;
    const int c0 = blockIdx.x * 256;
    const int tid = threadIdx.x;
    const int wid = tid >> 5, lane = tid & 31;
    const int g = lane >> 2, tig = lane & 3;
    const int wm = wid & 1, wn = wid >> 1;

    const int ra = tid >> 3, qa = tid & 7;

    float acc[8][4];
    #pragma unroll
    for (int i = 0; i < 8; i++)
        #pragma unroll
        for (int j = 0; j < 4; j++) acc[i][j] = 0.0f;

    {
        float4 va = *reinterpret_cast<const float4*>(
            &logits[((size_t)ra * N_ + n) * D_ + 4 * qa]);
        float4 vb[8];
        #pragma unroll
        for (int it = 0; it < 8; it++) {
            int i = tid + it * 256;
            int k = i >> 6, c4 = i & 63;
            vb[it] = *reinterpret_cast<const float4*>(
                &head[((size_t)n * D_ + k) * C_ + c0 + 4 * c4]);
        }
        float4 h, l;
        split4(va, h, l);
        *reinterpret_cast<float4*>(&Ah[ra * 36 + 4 * qa]) = h;
        *reinterpret_cast<float4*>(&Al[ra * 36 + 4 * qa]) = l;
        #pragma unroll
        for (int it = 0; it < 8; it++) {
            int i = tid + it * 256;
            int k = i >> 6, c4 = i & 63;
            split4(vb[it], h, l);
            *reinterpret_cast<float4*>(&Bh[k * 264 + 4 * c4]) = h;
            *reinterpret_cast<float4*>(&Bl[k * 264 + 4 * c4]) = l;
        }
    }
    __syncthreads();

    for (int ch = 0; ch < 8; ch++) {
        float4 na; float4 nb[8];
        if (ch < 7) {
            const int kb = (ch + 1) * 32;
            na = *reinterpret_cast<const float4*>(
                &logits[((size_t)ra * N_ + n) * D_ + kb + 4 * qa]);
            #pragma unroll
            for (int it = 0; it < 8; it++) {
                int i = tid + it * 256;
                int k = i >> 6, c4 = i & 63;
                nb[it] = *reinterpret_cast<const float4*>(
                    &head[((size_t)n * D_ + kb + k) * C_ + c0 + 4 * c4]);
            }
        }

        #pragma unroll
        for (int ks = 0; ks < 4; ks++) {
            const int kc = ks * 8 + tig;
            const int row = wm * 16 + g;
            unsigned ah[4], al[4];
            ah[0] = __float_as_uint(Ah[row * 36 + kc]);
            ah[1] = __float_as_uint(Ah[(row + 8) * 36 + kc]);
            ah[2] = __float_as_uint(Ah[row * 36 + kc + 4]);
            ah[3] = __float_as_uint(Ah[(row + 8) * 36 + kc + 4]);
            al[0] = __float_as_uint(Al[row * 36 + kc]);
            al[1] = __float_as_uint(Al[(row + 8) * 36 + kc]);
            al[2] = __float_as_uint(Al[row * 36 + kc + 4]);
            al[3] = __float_as_uint(Al[(row + 8) * 36 + kc + 4]);

            #pragma unroll
            for (int nf = 0; nf < 8; nf++) {
                int c = wn * 64 + nf * 8 + g;
                unsigned bh[2], bl[2];
                bh[0] = __float_as_uint(Bh[kc * 264 + c]);
                bh[1] = __float_as_uint(Bh[(kc + 4) * 264 + c]);
                bl[0] = __float_as_uint(Bl[kc * 264 + c]);
                bl[1] = __float_as_uint(Bl[(kc + 4) * 264 + c]);
                mma8(acc[nf], ah, bh);
                mma8(acc[nf], ah, bl);
                mma8(acc[nf], al, bh);
            }
        }
        __syncthreads();

        if (ch < 7) {
            float4 h, l;
            split4(na, h, l);
            *reinterpret_cast<float4*>(&Ah[ra * 36 + 4 * qa]) = h;
            *reinterpret_cast<float4*>(&Al[ra * 36 + 4 * qa]) = l;
            #pragma unroll
            for (int it = 0; it < 8; it++) {
                int i = tid + it * 256;
                int k = i >> 6, c4 = i & 63;
                split4(nb[it], h, l);
                *reinterpret_cast<float4*>(&Bh[k * 264 + 4 * c4]) = h;
                *reinterpret_cast<float4*>(&Bl[k * 264 + 4 * c4]) = l;
            }
            __syncthreads();
        }
    }

    const float inv_tau = 1.0f / tau[0];
    const int r = wm * 16 + g;
    #pragma unroll
    for (int nf = 0; nf < 8; nf++) {
        int c = c0 + wn * 64 + nf * 8 + 2 * tig;
        size_t b1 = ((size_t)r * N_ + n) * C_ + c;
        size_t b2 = ((size_t)(r + 8) * N_ + n) * C_ + c;
        float2 l1 = make_float2(acc[nf][0], acc[nf][1]);
        float2 l2 = make_float2(acc[nf][2], acc[nf][3]);
        *reinterpret_cast<float2*>(&la[b1]) = l1;
        *reinterpret_cast<float2*>(&la[b2]) = l2;
        float2 g1 = *reinterpret_cast<const float2*>(&gum[b1]);
        float2 g2 = *reinterpret_cast<const float2*>(&gum[b2]);
        *reinterpret_cast<float2*>(&g_v[b1]) =
            make_float2((l1.x + g1.x) * inv_tau, (l1.y + g1.y) * inv_tau);
        *reinterpret_cast<float2*>(&g_v[b2]) =
            make_float2((l2.x + g2.x) * inv_tau, (l2.y + g2.y) * inv_tau);
    }
}

// ============ Kernel 2: z = softmax(v) over C ============
__global__ __launch_bounds__(256) void k_softmax(float* __restrict__ z)
{
    __shared__ __align__(16) float sv[C_];
    __shared__ float redm[8];
    __shared__ float reds[8];
    const int m = blockIdx.x;
    const size_t base = (size_t)m * C_;
    const int tid = threadIdx.x;
    const int w = tid >> 5, l = tid & 31;

    float lmax = -3.4e38f;
    for (int c = tid * 4; c < C_; c += 1024) {
        float4 v = *reinterpret_cast<const float4*>(&g_v[base + c]);
        *reinterpret_cast<float4*>(&sv[c]) = v;
        lmax = fmaxf(lmax, fmaxf(fmaxf(v.x, v.y), fmaxf(v.z, v.w)));
    }
    #pragma unroll
    for (int off = 16; off; off >>= 1)
        lmax = fmaxf(lmax, __shfl_xor_sync(0xffffffffu, lmax, off));
    if (l == 0) redm[w] = lmax;
    __syncthreads();
    float bmax = redm[0];
    #pragma unroll
    for (int i = 1; i < 8; i++) bmax = fmaxf(bmax, redm[i]);

    float lsum = 0.0f;
    for (int c = tid * 4; c < C_; c += 1024) {
        float4 v = *reinterpret_cast<const float4*>(&sv[c]);
        v.x = __expf(v.x - bmax);
        v.y = __expf(v.y - bmax);
        v.z = __expf(v.z - bmax);
        v.w = __expf(v.w - bmax);
        *reinterpret_cast<float4*>(&sv[c]) = v;
        lsum += (v.x + v.y) + (v.z + v.w);
    }
    #pragma unroll
    for (int off = 16; off; off >>= 1)
        lsum += __shfl_xor_sync(0xffffffffu, lsum, off);
    if (l == 0) reds[w] = lsum;
    __syncthreads();
    float bsum = 0.0f;
    #pragma unroll
    for (int i = 0; i < 8; i++) bsum += reds[i];
    const float inv = 1.0f / bsum;

    for (int c = tid * 4; c < C_; c += 1024) {
        float4 v = *reinterpret_cast<const float4*>(&sv[c]);
        v.x *= inv; v.y *= inv; v.z *= inv; v.w *= inv;
        *reinterpret_cast<float4*>(&z[base + c]) = v;
    }
}

// ============ Kernel 3: q1 partials = z @ W^T, bf16x3, 8 K-splits ============
// grid (16 m-tiles, 8 k-splits) = 128 CTAs (~1 wave), block 512 (16 warps: 2m x 8n).
// CTA tile 128(M) x 256(N=D), K-slice 1024 in chunks of 32. bf16 hi/lo split,
// 3 passes (hh, hl, lh) of m16n8k16. Register-prefetch double buffering.
// smem planes (uint32 = bf16x2): Ah/Al [128][20], Bh/Bl [256][20] -> 61440 B.
#define G2S 20
#define G2_SMEM_BYTES (768 * G2S * 4)
__global__ __launch_bounds__(512) void k_gemm_cb_mma(
    const float* __restrict__ z, const float* __restrict__ W)
{
    extern __shared__ __align__(16) unsigned sm2[];
    unsigned* Ah = sm2;
    unsigned* Al = Ah + 128 * G2S;
    unsigned* Bh = Al + 128 * G2S;
    unsigned* Bl = Bh + 256 * G2S;

    const int m0 = blockIdx.x * 128;
    const int k0 = blockIdx.y * (C_ / KSPLIT);   // 1024
    float* part = g_q1p[blockIdx.y];
    const int tid = threadIdx.x;
    const int wid = tid >> 5, lane = tid & 31;
    const int g = lane >> 2, tig = lane & 3;
    const int wm = wid & 1, wn = wid >> 1;

    const int rs = tid >> 3, qs = tid & 7;   // staging: row, float4-quad

    float acc[4][4][4];
    #pragma unroll
    for (int i = 0; i < 4; i++)
        #pragma unroll
        for (int j = 0; j < 4; j++)
            #pragma unroll
            for (int t = 0; t < 4; t++) acc[i][j][t] = 0.0f;

    // prologue: stage chunk 0
    {
        float4 va[2], vb[4];
        #pragma unroll
        for (int it = 0; it < 2; it++) {
            int r = rs + it * 64;
            va[it] = *reinterpret_cast<const float4*>(
                &z[(size_t)(m0 + r) * C_ + k0 + 4 * qs]);
        }
        #pragma unroll
        for (int it = 0; it < 4; it++) {
            int r = rs + it * 64;
            vb[it] = *reinterpret_cast<const float4*>(
                &W[(size_t)r * C_ + k0 + 4 * qs]);
        }
        #pragma unroll
        for (int it = 0; it < 2; it++) {
            int r = rs + it * 64;
            unsigned h0, l0, h1, l1;
            bsplit2(va[it].x, va[it].y, h0, l0);
            bsplit2(va[it].z, va[it].w, h1, l1);
            Ah[r * G2S + 2 * qs] = h0; Ah[r * G2S + 2 * qs + 1] = h1;
            Al[r * G2S + 2 * qs] = l0; Al[r * G2S + 2 * qs + 1] = l1;
        }
        #pragma unroll
        for (int it = 0; it < 4; it++) {
            int r = rs + it * 64;
            unsigned h0, l0, h1, l1;
            bsplit2(vb[it].x, vb[it].y, h0, l0);
            bsplit2(vb[it].z, vb[it].w, h1, l1);
            Bh[r * G2S + 2 * qs] = h0; Bh[r * G2S + 2 * qs + 1] = h1;
            Bl[r * G2S + 2 * qs] = l0; Bl[r * G2S + 2 * qs + 1] = l1;
        }
    }
    __syncthreads();

    const int NCH = (C_ / KSPLIT) / 32;   // 32 chunks
    for (int ch = 0; ch < NCH; ch++) {
        float4 na[2], nb[4];
        if (ch < NCH - 1) {
            const int kb = k0 + (ch + 1) * 32;
            #pragma unroll
            for (int it = 0; it < 2; it++) {
                int r = rs + it * 64;
                na[it] = *reinterpret_cast<const float4*>(
                    &z[(size_t)(m0 + r) * C_ + kb + 4 * qs]);
            }
            #pragma unroll
            for (int it = 0; it < 4; it++) {
                int r = rs + it * 64;
                nb[it] = *reinterpret_cast<const float4*>(
                    &W[(size_t)r * C_ + kb + 4 * qs]);
            }
        }

        // compute: 2 k16-steps per chunk
        #pragma unroll
        for (int s = 0; s < 2; s++) {
            const int kp = s * 8 + tig;
            unsigned bh[4][2], bl[4][2];
            #pragma unroll
            for (int nf = 0; nf < 4; nf++) {
                int nn = wn * 32 + nf * 8 + g;
                bh[nf][0] = Bh[nn * G2S + kp];
                bh[nf][1] = Bh[nn * G2S + kp + 4];
                bl[nf][0] = Bl[nn * G2S + kp];
                bl[nf][1] = Bl[nn * G2S + kp + 4];
            }
            #pragma unroll
            for (int mf = 0; mf < 4; mf++) {
                int row = wm * 64 + mf * 16 + g;
                unsigned ah[4], al[4];
                ah[0] = Ah[row * G2S + kp];
                ah[1] = Ah[(row + 8) * G2S + kp];
                ah[2] = Ah[row * G2S + kp + 4];
                ah[3] = Ah[(row + 8) * G2S + kp + 4];
                al[0] = Al[row * G2S + kp];
                al[1] = Al[(row + 8) * G2S + kp];
                al[2] = Al[row * G2S + kp + 4];
                al[3] = Al[(row + 8) * G2S + kp + 4];
                #pragma unroll
                for (int nf = 0; nf < 4; nf++) {
                    mma16(acc[mf][nf], ah, bh[nf]);
                    mma16(acc[mf][nf], ah, bl[nf]);
                    mma16(acc[mf][nf], al, bh[nf]);
                }
            }
        }
        __syncthreads();

        if (ch < NCH - 1) {
            #pragma unroll
            for (int it = 0; it < 2; it++) {
                int r = rs + it * 64;
                unsigned h0, l0, h1, l1;
                bsplit2(na[it].x, na[it].y, h0, l0);
                bsplit2(na[it].z, na[it].w, h1, l1);
                Ah[r * G2S + 2 * qs] = h0; Ah[r * G2S + 2 * qs + 1] = h1;
                Al[r * G2S + 2 * qs] = l0; Al[r * G2S + 2 * qs + 1] = l1;
            }
            #pragma unroll
            for (int it = 0; it < 4; it++) {
                int r = rs + it * 64;
                unsigned h0, l0, h1, l1;
                bsplit2(nb[it].x, nb[it].y, h0, l0);
                bsplit2(nb[it].z, nb[it].w, h1, l1);
                Bh[r * G2S + 2 * qs] = h0; Bh[r * G2S + 2 * qs + 1] = h1;
                Bl[r * G2S + 2 * qs] = l0; Bl[r * G2S + 2 * qs + 1] = l1;
            }
            __syncthreads();
        }
    }

    #pragma unroll
    for (int mf = 0; mf < 4; mf++) {
        int r = m0 + wm * 64 + mf * 16 + g;
        #pragma unroll
        for (int nf = 0; nf < 4; nf++) {
            int d = wn * 32 + nf * 8 + 2 * tig;
            *reinterpret_cast<float2*>(&part[(size_t)r * D_ + d]) =
                make_float2(acc[mf][nf][0], acc[mf][nf][1]);
            *reinterpret_cast<float2*>(&part[(size_t)(r + 8) * D_ + d]) =
                make_float2(acc[mf][nf][2], acc[mf][nf][3]);
        }
    }
}

// ============ Kernel 4: q1 = sum of 8 partials ============
__global__ __launch_bounds__(256) void k_reduce()
{
    size_t i = ((size_t)blockIdx.x * 256 + threadIdx.x) * 4;
    float4 s = *reinterpret_cast<const float4*>(&g_q1p[0][i]);
    #pragma unroll
    for (int p = 1; p < KSPLIT; p++) {
        float4 v = *reinterpret_cast<const float4*>(&g_q1p[p][i]);
        s.x += v.x; s.y += v.y; s.z += v.z; s.w += v.w;
    }
    *reinterpret_cast<float4*>(&g_q1[i]) = s;
}

// ============ Kernel 5: quantized[b,n,j] = sum_d q1[b,n,d] * pos_map[n,d,j] ============
__global__ __launch_bounds__(256) void k_posmap(
    const float* __restrict__ pm, float* __restrict__ outq)
{
    __shared__ __align__(16) float qs[256 * 36];
    const int n = blockIdx.x;
    const int j0 = blockIdx.y * 64;
    const int tid = threadIdx.x;

    for (int i = tid; i < 32 * 256; i += 256) {
        int b = i >> 8, dd = i & 255;
        qs[dd * 36 + b] = g_q1[((size_t)b * N_ + n) * D_ + dd];
    }
    __syncthreads();

    const int jg = tid & 31, rg = tid >> 5;
    const int j  = j0 + jg * 2, r0 = rg * 4;

    u64 acc[2][2];
    acc[0][0] = acc[0][1] = acc[1][0] = acc[1][1] = 0ull;

    #pragma unroll 4
    for (int dd = 0; dd < 256; dd++) {
        float2 wv = *reinterpret_cast<const float2*>(&pm[((size_t)n * D_ + dd) * D_ + j]);
        u64 w0 = splat2(wv.x), w1 = splat2(wv.y);
        const u64* ap = reinterpret_cast<const u64*>(&qs[dd * 36 + r0]);
        u64 a0 = ap[0], a1 = ap[1];
        ffma2(acc[0][0], a0, w0);
        ffma2(acc[0][1], a0, w1);
        ffma2(acc[1][0], a1, w0);
        ffma2(acc[1][1], a1, w1);
    }

    #pragma unroll
    for (int p = 0; p < 2; p++) {
        float2 v0 = unpack2(acc[p][0]);
        float2 v1 = unpack2(acc[p][1]);
        int rlo = r0 + 2 * p;
        *reinterpret_cast<float2*>(&outq[((size_t)rlo * N_ + n) * D_ + j]) =
            make_float2(v0.x, v1.x);
        *reinterpret_cast<float2*>(&outq[((size_t)(rlo + 1) * N_ + n) * D_ + j]) =
            make_float2(v0.y, v1.y);
    }
}

extern "C" void kernel_launch(void* const* d_in, const int* in_sizes, int n_in,
                              void* d_out, int out_size)
{
    const float* logits  = (const float*)d_in[0];  // [B,N,D]
    const float* head    = (const float*)d_in[1];  // [N,D,C]
    const float* pos_map = (const float*)d_in[2];  // [N,D,D]
    const float* cbw     = (const float*)d_in[3];  // [D,C]
    const float* gum     = (const float*)d_in[4];  // [B,N,C]
    const float* tau     = (const float*)d_in[5];  // [1]

    float* out  = (float*)d_out;
    float* outq = out;                                   // quantized [B,N,D]
    float* la   = out + (size_t)B_ * N_ * D_;            // log_alpha [B,N,C]
    float* z    = la + (size_t)B_ * N_ * C_;             // z [B,N,C]

    const int g1_smem = G1_SMEM_FLOATS * 4;   // 76800 B
    cudaFuncSetAttribute(k_gemm_head_mma, cudaFuncAttributeMaxDynamicSharedMemorySize, g1_smem);
    cudaFuncSetAttribute(k_gemm_cb_mma,  cudaFuncAttributeMaxDynamicSharedMemorySize, G2_SMEM_BYTES);

    k_gemm_head_mma<<<dim3(C_ / 256, N_), 256, g1_smem>>>(logits, head, gum, tau, la);
    k_softmax<<<B_ * N_, 256>>>(z);
    k_gemm_cb_mma<<<dim3(16, KSPLIT), 512, G2_SMEM_BYTES>>>(z, cbw);
    k_reduce<<<(B_ * N_ * D_) / (256 * 4), 256>>>();
    k_posmap<<<dim3(N_, 4), 256>>>(pos_map, outq);
}